// round 3
// baseline (speedup 1.0000x reference)
#include <cuda_runtime.h>
#include <math.h>

#define BB 64
#define TT 512
#define DIN 512
#define HH 1024

#define NCOLBLK 32   // blocks along hidden dim
#define NBGRP 4      // independent batch groups
#define BROWS 16     // batch rows per block
#define BCOLS 32     // hidden cols per block
#define NTHR 256
#define WSTR 1028    // k-stride (floats) for Ws/As rows: 16B-aligned, bank-skewed

// packed fp32x2 FMA: d = a*b + d (elementwise on 2 packed floats)
#define FMA2(d, a, b) \
    asm("fma.rn.f32x2 %0, %1, %2, %0;" : "+l"(d) : "l"(a), "l"(b))

__device__ float g_buf0[(size_t)BB * TT * HH];
__device__ float g_buf1[(size_t)BB * TT * HH];

__device__ unsigned int          g_bar_count[NBGRP];
__device__ volatile unsigned int g_bar_gen[NBGRP];

__device__ __forceinline__ void group_barrier(int bg)
{
    __syncthreads();
    __threadfence();
    if (threadIdx.x == 0) {
        unsigned int gen = g_bar_gen[bg];
        unsigned int tkt = atomicAdd(&g_bar_count[bg], 1u);
        if (tkt == NCOLBLK - 1) {
            g_bar_count[bg] = 0;
            __threadfence();
            g_bar_gen[bg] = gen + 1;
        } else {
            while (g_bar_gen[bg] == gen) { }
        }
    }
    __syncthreads();
}

// ---------------------------------------------------------------------------
// pre-GEMM: C[M,N] = A[M,K] @ W[N,K]^T + (b0 + b1), FFMA2 version.
// Block tile 128(M) x 64(N), BK=8, 256 threads, micro-tile 8x4 per thread.
// Accumulators are f32x2 pairs along k (even/odd partials summed at the end).
// ---------------------------------------------------------------------------
#define PG_BM 128
#define PG_BN 64
#define PG_BK 8
#define PG_ASTR 12   // A smem row stride in floats (16B-aligned)

__global__ __launch_bounds__(256) void pre_gemm_kernel(
    const float* __restrict__ A,
    const float* __restrict__ W,
    const float* __restrict__ b0,
    const float* __restrict__ b1,
    float* __restrict__ C,
    int K, int N)
{
    __shared__ float As[PG_BM * PG_ASTR];     // [r][k], k-contiguous
    __shared__ ulonglong2 Wt[2 * 4 * 16];     // [g(2)][j(4)][tx(16)] of float4

    const int tid = threadIdx.x;
    const int tx = tid & 15;                  // col group: cols tx*4 .. tx*4+3
    const int ty = tid >> 4;                  // row group: rows ty*8 .. ty*8+7
    const int brow = blockIdx.y * PG_BM;
    const int bcol = blockIdx.x * PG_BN;

    unsigned long long acc[8][4];
#pragma unroll
    for (int i = 0; i < 8; i++)
#pragma unroll
        for (int j = 0; j < 4; j++) acc[i][j] = 0ull;

    const int lar = tid >> 1;                 // A loader row 0..127
    const int lak = (tid & 1) * 4;            // A loader k offset

    for (int k0 = 0; k0 < K; k0 += PG_BK) {
        // stage A tile (128 x 8)
        *(float4*)&As[lar * PG_ASTR + lak] =
            *(const float4*)&A[(size_t)(brow + lar) * K + k0 + lak];
        // stage W tile (64 x 8) into lane-consecutive compute layout
        if (tid < 128) {
            int c  = tid >> 1;                // 0..63
            int g  = tid & 1;                 // k-group (4k each)
            int j  = c & 3;
            int txs = c >> 2;
            Wt[(g * 4 + j) * 16 + txs] =
                *(const ulonglong2*)&W[(size_t)(bcol + c) * K + k0 + g * 4];
        }
        __syncthreads();

#pragma unroll
        for (int g = 0; g < 2; g++) {
            ulonglong2 w[4];
#pragma unroll
            for (int j = 0; j < 4; j++) w[j] = Wt[(g * 4 + j) * 16 + tx];
#pragma unroll
            for (int i = 0; i < 8; i++) {
                ulonglong2 a = *(const ulonglong2*)&As[(ty * 8 + i) * PG_ASTR + g * 4];
#pragma unroll
                for (int j = 0; j < 4; j++) {
                    FMA2(acc[i][j], a.x, w[j].x);
                    FMA2(acc[i][j], a.y, w[j].y);
                }
            }
        }
        __syncthreads();
    }

    const int col = bcol + tx * 4;
    float bias[4];
#pragma unroll
    for (int j = 0; j < 4; j++) bias[j] = b0[col + j] + b1[col + j];

#pragma unroll
    for (int i = 0; i < 8; i++) {
        const int row = brow + ty * 8 + i;
        float4 o;
        float2 f;
        f = *(float2*)&acc[i][0]; o.x = f.x + f.y + bias[0];
        f = *(float2*)&acc[i][1]; o.y = f.x + f.y + bias[1];
        f = *(float2*)&acc[i][2]; o.z = f.x + f.y + bias[2];
        f = *(float2*)&acc[i][3]; o.w = f.x + f.y + bias[3];
        *(float4*)&C[(size_t)row * N + col] = o;
    }
}

// ---------------------------------------------------------------------------
// Persistent recurrent layer, FFMA2 version.
// Block: 16 rows x 32 cols. 8 warps, warp tile 8x8, lane micro-tile 2 rows.
// Ws: [c][k] (k-contiguous, stride WSTR) - loaded once, held for all T steps.
// As: [r][k] (stride WSTR) - restaged per step.
// k-paired f32x2 accumulation: conflict-free LDS.128 on both operands.
// ---------------------------------------------------------------------------
__global__ __launch_bounds__(NTHR, 1) void rnn_layer_kernel(
    const float* __restrict__ pre,
    float* __restrict__ hbase,
    const float* __restrict__ Whh)
{
    extern __shared__ float sm[];
    float* Ws = sm;                     // [32][WSTR]
    float* As = sm + BCOLS * WSTR;      // [16][WSTR]

    const int tid  = threadIdx.x;
    const int bg   = blockIdx.y;
    const int bcol = blockIdx.x * BCOLS;
    const int brow = bg * BROWS;
    const size_t row_stride = (size_t)TT * HH;

    // one-time W slice load: Ws[c][k] = Whh[bcol+c][k]  (coalesced float4)
    for (int i = tid; i < BCOLS * (HH / 4); i += NTHR) {
        int c  = i >> 8;
        int kq = (i & 255) * 4;
        *(float4*)&Ws[c * WSTR + kq] =
            *(const float4*)&Whh[(size_t)(bcol + c) * HH + kq];
    }
    __syncthreads();

    const int lid = tid & 31;
    const int wid = tid >> 5;           // 0..7
    const int wr  = wid & 1;            // row tile (8 rows each)
    const int wc  = wid >> 1;           // col tile (8 cols each)
    const int c8  = lid >> 2;           // 0..7
    const int rg  = lid & 3;            // 0..3
    const int lrow = wr * 8 + rg * 2;   // local rows lrow, lrow+1
    const int lcol = wc * 8 + c8;

    const float* wrow = Ws + lcol * WSTR;
    const float* ar0  = As + lrow * WSTR;
    const float* ar1  = ar0 + WSTR;

    for (int t = 0; t < TT; t++) {
        unsigned long long a00 = 0ull, a01 = 0ull, a10 = 0ull, a11 = 0ull;

        if (t > 0) {
            // stage h(t-1)[brow..brow+15][:] into As
            const float* hsrc = hbase + (size_t)(t - 1) * HH;
            for (int i = tid; i < BROWS * (HH / 4); i += NTHR) {
                int r  = i >> 8;
                int kq = (i & 255) * 4;
                *(float4*)&As[r * WSTR + kq] =
                    *(const float4*)&hsrc[(size_t)(brow + r) * row_stride + kq];
            }
            __syncthreads();

#pragma unroll 8
            for (int k = 0; k < HH; k += 4) {
                ulonglong2 w  = *(const ulonglong2*)(wrow + k);
                ulonglong2 v0 = *(const ulonglong2*)(ar0 + k);
                ulonglong2 v1 = *(const ulonglong2*)(ar1 + k);
                FMA2(a00, v0.x, w.x);
                FMA2(a01, v0.y, w.y);
                FMA2(a10, v1.x, w.x);
                FMA2(a11, v1.y, w.y);
            }
        }

        float2 f0 = *(float2*)&a00;
        float2 f1 = *(float2*)&a01;
        float2 f2 = *(float2*)&a10;
        float2 f3 = *(float2*)&a11;
        float s0 = f0.x + f0.y + f1.x + f1.y;
        float s1 = f2.x + f2.y + f3.x + f3.y;

        const size_t ob0 = (size_t)(brow + lrow) * row_stride + (size_t)t * HH
                         + bcol + lcol;
        const size_t ob1 = ob0 + row_stride;
        hbase[ob0] = tanhf(pre[ob0] + s0);
        hbase[ob1] = tanhf(pre[ob1] + s1);

        group_barrier(bg);   // entry syncthreads also protects As reuse
    }
}

// ---------------------------------------------------------------------------
__global__ void finalize_kernel(float* __restrict__ out)
{
    int i = blockIdx.x * blockDim.x + threadIdx.x;   // over B*H
    if (i >= BB * HH) return;
    int b = i / HH;
    int h = i - b * HH;
    float* hfin = out + (size_t)BB * TT * HH;
    size_t src = (size_t)b * TT * HH + (size_t)(TT - 1) * HH + h;
    hfin[i] = g_buf0[src];
    hfin[(size_t)BB * HH + i] = out[src];
}

// ---------------------------------------------------------------------------

extern "C" void kernel_launch(void* const* d_in, const int* in_sizes, int n_in,
                              void* d_out, int out_size)
{
    const float* x      = (const float*)d_in[0];
    const float* W_ih0  = (const float*)d_in[1];
    const float* W_hh0  = (const float*)d_in[2];
    const float* b_ih0  = (const float*)d_in[3];
    const float* b_hh0  = (const float*)d_in[4];
    const float* W_ih1  = (const float*)d_in[5];
    const float* W_hh1  = (const float*)d_in[6];
    const float* b_ih1  = (const float*)d_in[7];
    const float* b_hh1  = (const float*)d_in[8];
    float* out = (float*)d_out;

    void* p0; cudaGetSymbolAddress(&p0, g_buf0);
    void* p1; cudaGetSymbolAddress(&p1, g_buf1);
    float* buf0 = (float*)p0;
    float* buf1 = (float*)p1;

    const int rnn_smem = (BCOLS + BROWS) * WSTR * (int)sizeof(float); // 197376
    cudaFuncSetAttribute(rnn_layer_kernel,
                         cudaFuncAttributeMaxDynamicSharedMemorySize, rnn_smem);

    // 1) pre0 = X @ W_ih0^T + b_ih0 + b_hh0
    {
        dim3 grid(HH / PG_BN, (BB * TT) / PG_BM);
        pre_gemm_kernel<<<grid, 256>>>(x, W_ih0, b_ih0, b_hh0, buf0, DIN, HH);
    }

    // 2) layer-0 recurrence (persistent, in place over buf0)
    {
        dim3 grid(NCOLBLK, NBGRP);
        rnn_layer_kernel<<<grid, NTHR, rnn_smem>>>(buf0, buf0, W_hh0);
    }

    // 3) pre1 = H0 @ W_ih1^T + b_ih1 + b_hh1
    {
        dim3 grid(HH / PG_BN, (BB * TT) / PG_BM);
        pre_gemm_kernel<<<grid, 256>>>(buf0, W_ih1, b_ih1, b_hh1, buf1, HH, HH);
    }

    // 4) layer-1 recurrence (persistent, writes h1 into outputs region)
    {
        dim3 grid(NCOLBLK, NBGRP);
        rnn_layer_kernel<<<grid, NTHR, rnn_smem>>>(buf1, out, W_hh1);
    }

    // 5) h_final
    finalize_kernel<<<(BB * HH + 255) / 256, 256>>>(out);
}

// round 5
// speedup vs baseline: 1.6419x; 1.6419x over previous
#include <cuda_runtime.h>
#include <cuda_bf16.h>
#include <math.h>
#include <stdint.h>

#define BB 64
#define TT 512
#define DIN 512
#define HH 1024

#define NBLK 64     // persistent blocks (16 hidden cols each)
#define NCOLS 16
#define NTHR 256

// SMEM layout (bytes from dynamic smem base; all offsets 16B-aligned)
#define AROWB 528            // A row stride: 256 bf16 + 8 pad = 528 B
#define WROWB 2064           // W row stride: 1024 bf16 + 8 pad = 2064 B
#define SM_WHI 0
#define SM_WLO (NCOLS * WROWB)            // 33024
#define SM_A   (2 * NCOLS * WROWB)        // 66048
#define A_ONE  (64 * AROWB)               // 33792 (one hi or lo plane)
#define ABUFP  (2 * A_ONE)                // 67584 (hi+lo per buffer)
#define SM_TOTAL (SM_A + 2 * ABUFP)       // 201216

// Scratch: buf0 holds pre0 then h0 in place; buf1 holds pre1. h1 -> d_out.
__device__ float g_buf0[(size_t)BB * TT * HH];
__device__ float g_buf1[(size_t)BB * TT * HH];
// Current h(t) as bf16 hi/lo split (rewritten every step)
__device__ __nv_bfloat16 g_hhi[(size_t)BB * HH];
__device__ __nv_bfloat16 g_hlo[(size_t)BB * HH];

// 64-block grid barrier (generation-based; replay-safe)
__device__ unsigned int          g_bar_count;
__device__ volatile unsigned int g_bar_gen;

__device__ __forceinline__ void grid_barrier64()
{
    __syncthreads();
    __threadfence();
    if (threadIdx.x == 0) {
        unsigned int gen = g_bar_gen;
        unsigned int tkt = atomicAdd(&g_bar_count, 1u);
        if (tkt == NBLK - 1) {
            g_bar_count = 0;
            __threadfence();
            g_bar_gen = gen + 1;
        } else {
            while (g_bar_gen == gen) { }
        }
    }
    __syncthreads();
}

// ---------------------- PTX helpers (sm_80+ features only) ----------------
__device__ __forceinline__ uint32_t smem_u32(const void* p) {
    uint32_t a;
    asm("{ .reg .u64 t; cvta.to.shared.u64 t, %1; cvt.u32.u64 %0, t; }"
        : "=r"(a) : "l"(p));
    return a;
}
__device__ __forceinline__ void cp16(uint32_t dst, const void* src) {
    asm volatile("cp.async.cg.shared.global [%0], [%1], 16;"
                 :: "r"(dst), "l"(src));
}
__device__ __forceinline__ void cp_commit() {
    asm volatile("cp.async.commit_group;");
}
__device__ __forceinline__ void ldsm4(uint32_t* r, uint32_t addr) {
    asm volatile("ldmatrix.sync.aligned.m8n8.x4.shared.b16 {%0,%1,%2,%3}, [%4];"
                 : "=r"(r[0]), "=r"(r[1]), "=r"(r[2]), "=r"(r[3]) : "r"(addr));
}
__device__ __forceinline__ void ldsm2(uint32_t* r, uint32_t addr) {
    asm volatile("ldmatrix.sync.aligned.m8n8.x2.shared.b16 {%0,%1}, [%2];"
                 : "=r"(r[0]), "=r"(r[1]) : "r"(addr));
}
__device__ __forceinline__ void mma_bf16(float& c0, float& c1, float& c2, float& c3,
                                         const uint32_t* a, const uint32_t* b) {
    asm volatile(
        "mma.sync.aligned.m16n8k16.row.col.f32.bf16.bf16.f32 "
        "{%0,%1,%2,%3}, {%4,%5,%6,%7}, {%8,%9}, {%0,%1,%2,%3};"
        : "+f"(c0), "+f"(c1), "+f"(c2), "+f"(c3)
        : "r"(a[0]), "r"(a[1]), "r"(a[2]), "r"(a[3]), "r"(b[0]), "r"(b[1]));
}
__device__ __forceinline__ uint32_t pack_bf16(float x, float y) {
    __nv_bfloat162 v = __floats2bfloat162_rn(x, y);
    return *(uint32_t*)&v;
}

// ---------------------------------------------------------------------------
// pre-GEMM (R2 version, known good): C = A @ W^T + (b0 + b1)
// ---------------------------------------------------------------------------
__global__ __launch_bounds__(256) void pre_gemm_kernel(
    const float* __restrict__ A,
    const float* __restrict__ W,
    const float* __restrict__ b0,
    const float* __restrict__ b1,
    float* __restrict__ C,
    int K, int N)
{
    __shared__ float As[16][64];
    __shared__ float Ws[16][64];

    const int tid = threadIdx.x;
    const int tx = tid & 15;
    const int ty = tid >> 4;
    const int block_row = blockIdx.y * 64;
    const int block_col = blockIdx.x * 64;

    const int lrow = tid >> 2;
    const int lk   = (tid & 3) * 4;

    float acc[4][4] = {};

    for (int k0 = 0; k0 < K; k0 += 16) {
        float4 av = *(const float4*)&A[(size_t)(block_row + lrow) * K + k0 + lk];
        float4 wv = *(const float4*)&W[(size_t)(block_col + lrow) * K + k0 + lk];
        As[lk + 0][lrow] = av.x; As[lk + 1][lrow] = av.y;
        As[lk + 2][lrow] = av.z; As[lk + 3][lrow] = av.w;
        Ws[lk + 0][lrow] = wv.x; Ws[lk + 1][lrow] = wv.y;
        Ws[lk + 2][lrow] = wv.z; Ws[lk + 3][lrow] = wv.w;
        __syncthreads();

#pragma unroll
        for (int kk = 0; kk < 16; kk++) {
            float4 a4 = *(const float4*)&As[kk][ty * 4];
            float4 w4 = *(const float4*)&Ws[kk][tx * 4];
            float a[4] = {a4.x, a4.y, a4.z, a4.w};
            float w[4] = {w4.x, w4.y, w4.z, w4.w};
#pragma unroll
            for (int i = 0; i < 4; i++)
#pragma unroll
                for (int j = 0; j < 4; j++)
                    acc[i][j] += a[i] * w[j];
        }
        __syncthreads();
    }

    const int col = block_col + tx * 4;
    float bias[4];
#pragma unroll
    for (int j = 0; j < 4; j++) bias[j] = b0[col + j] + b1[col + j];

#pragma unroll
    for (int i = 0; i < 4; i++) {
        const int row = block_row + ty * 4 + i;
        float4 r;
        r.x = acc[i][0] + bias[0];
        r.y = acc[i][1] + bias[1];
        r.z = acc[i][2] + bias[2];
        r.w = acc[i][3] + bias[3];
        *(float4*)&C[(size_t)row * N + col] = r;
    }
}

// ---------------------------------------------------------------------------
// Persistent HMMA recurrent layer.
// 64 blocks; block owns hidden cols [bcol, bcol+16) for all 64 batch rows.
// W slice bf16 hi/lo in SMEM [n][k] (ldmatrix-direct), loaded once.
// Per step: h(t-1) hi/lo staged in 4 K-chunks of 256 via cp.async (depth-1
// prefetch), 3 mma.sync passes (AhBh + AhBl + AlBh), fp32 C in registers.
// 8 warps = 4 m-tiles x 2 n-tiles (m16n8k16).
// ---------------------------------------------------------------------------
__global__ __launch_bounds__(NTHR, 1) void rnn_layer_tc(
    const float* __restrict__ pre,
    float* __restrict__ hbase,
    const float* __restrict__ Whh)
{
    extern __shared__ char smb[];
    const uint32_t smu = smem_u32(smb);

    const int tid  = threadIdx.x;
    const int wid  = tid >> 5;
    const int lane = tid & 31;
    const int bcol = blockIdx.x * NCOLS;

    // --- one-time W slice load: fp32 -> bf16 hi/lo, [n][k] padded rows ---
    for (int i = tid; i < NCOLS * HH; i += NTHR) {
        int n = i >> 10;
        int k = i & 1023;
        float v = Whh[(size_t)(bcol + n) * HH + k];
        __nv_bfloat16 hi = __float2bfloat16(v);
        __nv_bfloat16 lo = __float2bfloat16(v - __bfloat162float(hi));
        *(__nv_bfloat16*)(smb + SM_WHI + n * WROWB + k * 2) = hi;
        *(__nv_bfloat16*)(smb + SM_WLO + n * WROWB + k * 2) = lo;
    }
    __syncthreads();

    // warp tile: mt in 0..3 (16 batch rows), nt in 0..1 (8 cols)
    const int mt = wid >> 1;
    const int nt = wid & 1;

    // ldmatrix lane address components
    const int grp = lane >> 3;          // 0..3
    const int rin = lane & 7;
    // A: matrices [m0-7,k0-7],[m8-15,k0-7],[m0-7,k8-15],[m8-15,k8-15]
    const uint32_t a_lane_off =
        (uint32_t)((mt * 16 + (grp & 1) * 8 + rin) * AROWB + (grp >> 1) * 16);
    // B: x2 uses lanes 0-15; replicate pattern on upper half
    const int l16 = lane & 15;
    const uint32_t b_lane_off =
        (uint32_t)((nt * 8 + (l16 & 7)) * WROWB + (l16 >> 3) * 16);

    // staging decomposition: 16B unit u = tid + i*256 ; row = u>>5, ku = u&31
    const size_t row_stride = (size_t)TT * HH;

    for (int t = 0; t < TT; t++) {
        float c0 = 0.f, c1 = 0.f, c2 = 0.f, c3 = 0.f;

        if (t > 0) {
            // ---- stage chunk 0 ----
#pragma unroll
            for (int i = 0; i < 8; i++) {
                int u = tid + i * NTHR;
                int row = u >> 5;
                int ku  = u & 31;
                uint32_t d = smu + SM_A + (uint32_t)(row * AROWB + ku * 16);
                const size_t gsrc = (size_t)row * HH + ku * 8;
                cp16(d,         g_hhi + gsrc);
                cp16(d + A_ONE, g_hlo + gsrc);
            }
            cp_commit();

#pragma unroll
            for (int c = 0; c < 4; c++) {
                if (c < 3) {
                    const uint32_t bb = smu + SM_A + ((c + 1) & 1) * ABUFP;
#pragma unroll
                    for (int i = 0; i < 8; i++) {
                        int u = tid + i * NTHR;
                        int row = u >> 5;
                        int ku  = u & 31;
                        uint32_t d = bb + (uint32_t)(row * AROWB + ku * 16);
                        const size_t gsrc = (size_t)row * HH + (c + 1) * 256 + ku * 8;
                        cp16(d,         g_hhi + gsrc);
                        cp16(d + A_ONE, g_hlo + gsrc);
                    }
                    cp_commit();
                    asm volatile("cp.async.wait_group 1;");
                } else {
                    asm volatile("cp.async.wait_group 0;");
                }
                __syncthreads();

                // ---- MMA over this chunk's 16 k-steps ----
                const uint32_t ahb = smu + SM_A + (c & 1) * ABUFP + a_lane_off;
                const uint32_t alb = ahb + A_ONE;
                const uint32_t bhb = smu + SM_WHI + b_lane_off + (uint32_t)(c * 512);
                const uint32_t blb = smu + SM_WLO + b_lane_off + (uint32_t)(c * 512);
#pragma unroll
                for (int s = 0; s < 16; s++) {
                    uint32_t ah[4], al[4], bh[2], bl[2];
                    ldsm4(ah, ahb + s * 32);
                    ldsm4(al, alb + s * 32);
                    ldsm2(bh, bhb + s * 32);
                    ldsm2(bl, blb + s * 32);
                    mma_bf16(c0, c1, c2, c3, ah, bh);
                    mma_bf16(c0, c1, c2, c3, ah, bl);
                    mma_bf16(c0, c1, c2, c3, al, bh);
                }
                __syncthreads();
            }
        }

        // ---- epilogue: C frag + pre -> tanh -> h (fp32) + hi/lo (bf16) ----
        {
            const int gid = lane >> 2;
            const int tig = lane & 3;
            const int m0 = mt * 16 + gid;
            const int m1 = m0 + 8;
            const int nc = bcol + nt * 8 + tig * 2;

            const size_t o0 = (size_t)m0 * row_stride + (size_t)t * HH + nc;
            const size_t o1 = (size_t)m1 * row_stride + (size_t)t * HH + nc;

            float2 p0 = *(const float2*)&pre[o0];
            float2 p1 = *(const float2*)&pre[o1];
            float h00 = tanhf(p0.x + c0);
            float h01 = tanhf(p0.y + c1);
            float h10 = tanhf(p1.x + c2);
            float h11 = tanhf(p1.y + c3);
            float2 r0 = make_float2(h00, h01);
            float2 r1 = make_float2(h10, h11);
            *(float2*)&hbase[o0] = r0;
            *(float2*)&hbase[o1] = r1;

            // bf16 hi/lo state for next step
            __nv_bfloat16 e00 = __float2bfloat16(h00);
            __nv_bfloat16 e01 = __float2bfloat16(h01);
            __nv_bfloat16 e10 = __float2bfloat16(h10);
            __nv_bfloat16 e11 = __float2bfloat16(h11);
            uint32_t hi0 = pack_bf16(h00, h01);   // rn-packed hi
            uint32_t hi1 = pack_bf16(h10, h11);
            // recompute hi halves consistently with pack (rn rounding both ways)
            float f00 = __bfloat162float(__nv_bfloat16(e00));
            float f01 = __bfloat162float(__nv_bfloat16(e01));
            float f10 = __bfloat162float(__nv_bfloat16(e10));
            float f11 = __bfloat162float(__nv_bfloat16(e11));
            uint32_t lo0 = pack_bf16(h00 - f00, h01 - f01);
            uint32_t lo1 = pack_bf16(h10 - f10, h11 - f11);

            *(uint32_t*)&g_hhi[(size_t)m0 * HH + nc] = hi0;
            *(uint32_t*)&g_hhi[(size_t)m1 * HH + nc] = hi1;
            *(uint32_t*)&g_hlo[(size_t)m0 * HH + nc] = lo0;
            *(uint32_t*)&g_hlo[(size_t)m1 * HH + nc] = lo1;
        }

        grid_barrier64();
    }
}

// ---------------------------------------------------------------------------
__global__ void finalize_kernel(float* __restrict__ out)
{
    int i = blockIdx.x * blockDim.x + threadIdx.x;   // over B*H
    if (i >= BB * HH) return;
    int b = i / HH;
    int h = i - b * HH;
    float* hfin = out + (size_t)BB * TT * HH;
    size_t src = (size_t)b * TT * HH + (size_t)(TT - 1) * HH + h;
    hfin[i] = g_buf0[src];
    hfin[(size_t)BB * HH + i] = out[src];
}

// ---------------------------------------------------------------------------

extern "C" void kernel_launch(void* const* d_in, const int* in_sizes, int n_in,
                              void* d_out, int out_size)
{
    const float* x      = (const float*)d_in[0];
    const float* W_ih0  = (const float*)d_in[1];
    const float* W_hh0  = (const float*)d_in[2];
    const float* b_ih0  = (const float*)d_in[3];
    const float* b_hh0  = (const float*)d_in[4];
    const float* W_ih1  = (const float*)d_in[5];
    const float* W_hh1  = (const float*)d_in[6];
    const float* b_ih1  = (const float*)d_in[7];
    const float* b_hh1  = (const float*)d_in[8];
    float* out = (float*)d_out;

    void* p0; cudaGetSymbolAddress(&p0, g_buf0);
    void* p1; cudaGetSymbolAddress(&p1, g_buf1);
    float* buf0 = (float*)p0;
    float* buf1 = (float*)p1;

    cudaFuncSetAttribute(rnn_layer_tc,
                         cudaFuncAttributeMaxDynamicSharedMemorySize, SM_TOTAL);

    // 1) pre0 = X @ W_ih0^T + b_ih0 + b_hh0
    {
        dim3 grid(HH / 64, (BB * TT) / 64);
        pre_gemm_kernel<<<grid, 256>>>(x, W_ih0, b_ih0, b_hh0, buf0, DIN, HH);
    }

    // 2) layer-0 recurrence (HMMA persistent, in place over buf0)
    rnn_layer_tc<<<NBLK, NTHR, SM_TOTAL>>>(buf0, buf0, W_hh0);

    // 3) pre1 = H0 @ W_ih1^T + b_ih1 + b_hh1
    {
        dim3 grid(HH / 64, (BB * TT) / 64);
        pre_gemm_kernel<<<grid, 256>>>(buf0, W_ih1, b_ih1, b_hh1, buf1, HH, HH);
    }

    // 4) layer-1 recurrence (HMMA persistent, writes h1 into outputs region)
    rnn_layer_tc<<<NBLK, NTHR, SM_TOTAL>>>(buf1, out, W_hh1);

    // 5) h_final
    finalize_kernel<<<(BB * HH + 255) / 256, 256>>>(out);
}

// round 6
// speedup vs baseline: 1.9876x; 1.2106x over previous
#include <cuda_runtime.h>
#include <cuda_bf16.h>
#include <math.h>
#include <stdint.h>

#define BB 64
#define TT 512
#define DIN 512
#define HH 1024

#define NBLK 64     // persistent rnn blocks (16 hidden cols each)
#define NCOLS 16
#define NTHR 256

// rnn SMEM layout (bytes from dynamic smem base; 16B-aligned offsets)
#define AROWB 528            // A row stride: 256 bf16 + 8 pad
#define WROWB 2064           // W row stride: 1024 bf16 + 8 pad
#define SM_WHI 0
#define SM_WLO (NCOLS * WROWB)            // 33024
#define SM_A   (2 * NCOLS * WROWB)        // 66048
#define A_ONE  (64 * AROWB)               // 33792 (one hi or lo plane)
#define ABUFP  (2 * A_ONE)                // 67584 (hi+lo per buffer)
#define SM_TOTAL (SM_A + 2 * ABUFP)       // 201216

// Scratch: buf0 holds pre0 then h0 in place; buf1 holds pre1. h1 -> d_out.
__device__ float g_buf0[(size_t)BB * TT * HH];
__device__ float g_buf1[(size_t)BB * TT * HH];
// Current h(t) as bf16 hi/lo split (rewritten every step)
__device__ __nv_bfloat16 g_hhi[(size_t)BB * HH];
__device__ __nv_bfloat16 g_hlo[(size_t)BB * HH];
// bf16 hi/lo split of the big GEMM A operand (X, then H0) and W operand
__device__ __nv_bfloat16 g_ahi[(size_t)BB * TT * HH];
__device__ __nv_bfloat16 g_alo[(size_t)BB * TT * HH];
__device__ __nv_bfloat16 g_whi[(size_t)HH * HH];
__device__ __nv_bfloat16 g_wlo[(size_t)HH * HH];

// 64-block grid barrier (generation-based; replay-safe)
__device__ unsigned int          g_bar_count;
__device__ volatile unsigned int g_bar_gen;

__device__ __forceinline__ void grid_barrier64()
{
    __syncthreads();
    __threadfence();
    if (threadIdx.x == 0) {
        unsigned int gen = g_bar_gen;
        unsigned int tkt = atomicAdd(&g_bar_count, 1u);
        if (tkt == NBLK - 1) {
            g_bar_count = 0;
            __threadfence();
            g_bar_gen = gen + 1;
        } else {
            while (g_bar_gen == gen) { }
        }
    }
    __syncthreads();
}

// ---------------------- PTX helpers (sm_80+ features only) ----------------
__device__ __forceinline__ uint32_t smem_u32(const void* p) {
    uint32_t a;
    asm("{ .reg .u64 t; cvta.to.shared.u64 t, %1; cvt.u32.u64 %0, t; }"
        : "=r"(a) : "l"(p));
    return a;
}
__device__ __forceinline__ void cp16(uint32_t dst, const void* src) {
    asm volatile("cp.async.cg.shared.global [%0], [%1], 16;"
                 :: "r"(dst), "l"(src));
}
__device__ __forceinline__ void cp_commit() {
    asm volatile("cp.async.commit_group;");
}
__device__ __forceinline__ void ldsm4(uint32_t* r, uint32_t addr) {
    asm volatile("ldmatrix.sync.aligned.m8n8.x4.shared.b16 {%0,%1,%2,%3}, [%4];"
                 : "=r"(r[0]), "=r"(r[1]), "=r"(r[2]), "=r"(r[3]) : "r"(addr));
}
__device__ __forceinline__ void mma_bf16v(float* c, const uint32_t* a,
                                          const uint32_t* b) {
    asm volatile(
        "mma.sync.aligned.m16n8k16.row.col.f32.bf16.bf16.f32 "
        "{%0,%1,%2,%3}, {%4,%5,%6,%7}, {%8,%9}, {%0,%1,%2,%3};"
        : "+f"(c[0]), "+f"(c[1]), "+f"(c[2]), "+f"(c[3])
        : "r"(a[0]), "r"(a[1]), "r"(a[2]), "r"(a[3]), "r"(b[0]), "r"(b[1]));
}
__device__ __forceinline__ uint32_t pack_bf16(float x, float y) {
    __nv_bfloat162 v = __floats2bfloat162_rn(x, y);
    return *(uint32_t*)&v;
}

// ---------------------------------------------------------------------------
// fp32 -> bf16 hi/lo split (elementwise, grid-stride, n % 4 == 0)
// ---------------------------------------------------------------------------
__global__ void conv_split_kernel(const float* __restrict__ in,
                                  __nv_bfloat16* __restrict__ hi,
                                  __nv_bfloat16* __restrict__ lo, int n)
{
    int stride = gridDim.x * blockDim.x * 4;
    for (int i = (blockIdx.x * blockDim.x + threadIdx.x) * 4; i < n; i += stride) {
        float4 f = *(const float4*)&in[i];
        __nv_bfloat16 hx = __float2bfloat16(f.x);
        __nv_bfloat16 hy = __float2bfloat16(f.y);
        __nv_bfloat16 hz = __float2bfloat16(f.z);
        __nv_bfloat16 hw = __float2bfloat16(f.w);
        uint32_t h0 = pack_bf16(f.x, f.y);
        uint32_t h1 = pack_bf16(f.z, f.w);
        uint32_t l0 = pack_bf16(f.x - __bfloat162float(hx), f.y - __bfloat162float(hy));
        uint32_t l1 = pack_bf16(f.z - __bfloat162float(hz), f.w - __bfloat162float(hw));
        *(uint2*)&hi[i] = make_uint2(h0, h1);
        *(uint2*)&lo[i] = make_uint2(l0, l1);
    }
}

// ---------------------------------------------------------------------------
// HMMA pre-GEMM: C[M,1024] = Ah@(Wh+Wl)^T + Al@Wh^T + (b0 + b1)
// (3-pass bf16 hi/lo = fp32-grade). Block 128(M) x 64(N), BK=32, 256 thr,
// 8 warps = 4m x 2n, warp tile 32x32, cp.async double-buffered.
// ---------------------------------------------------------------------------
#define PRS 80            // smem row stride (32 bf16 = 64B + 16 pad)
#define P_AHI 0
#define P_ALO 10240
#define P_BHI 20480
#define P_BLO 25600
#define P_STAGE 30720
#define P_SMEM (2 * P_STAGE)

__global__ __launch_bounds__(256) void hmma_pre_gemm(
    const __nv_bfloat16* __restrict__ Ahi,
    const __nv_bfloat16* __restrict__ Alo,
    const __nv_bfloat16* __restrict__ Whi,
    const __nv_bfloat16* __restrict__ Wlo,
    const float* __restrict__ b0,
    const float* __restrict__ b1,
    float* __restrict__ C,
    int K)
{
    extern __shared__ char smb[];
    const uint32_t smu = smem_u32(smb);
    const int tid  = threadIdx.x;
    const int lane = tid & 31;
    const int wid  = tid >> 5;
    const int wm   = wid >> 1;
    const int wn   = wid & 1;
    const int brow = blockIdx.y * 128;
    const int bcol = blockIdx.x * 64;

    float acc[2][4][4];
#pragma unroll
    for (int mi = 0; mi < 2; mi++)
#pragma unroll
        for (int nj = 0; nj < 4; nj++)
#pragma unroll
            for (int q = 0; q < 4; q++) acc[mi][nj][q] = 0.f;

    const int grp = lane >> 3, rin = lane & 7;
    // A x4: r0=(m0-7,k0) r1=(m8-15,k0) r2=(m0-7,k8) r3=(m8-15,k8)
    const uint32_t a_off = (uint32_t)((wm * 32 + (grp & 1) * 8 + rin) * PRS
                                      + (grp >> 1) * 16);
    // B x4: r0=(n0-7,k0) r1=(n0-7,k8) r2=(n8-15,k0) r3=(n8-15,k8)
    const uint32_t b_off = (uint32_t)((wn * 32 + (grp >> 1) * 8 + rin) * PRS
                                      + (grp & 1) * 16);

    const int KT = K >> 5;

    auto issue_stage = [&](int kt) {
        const uint32_t sb = smu + (uint32_t)((kt & 1) * P_STAGE);
        const int k0 = kt * 32;
#pragma unroll
        for (int i = 0; i < 6; i++) {
            int u = tid + i * 256;
            if (u < 1024) {
                int plane = u >> 9, idx = u & 511;
                int row = idx >> 2, seg = idx & 3;
                const __nv_bfloat16* src = (plane ? Alo : Ahi)
                    + (size_t)(brow + row) * K + k0 + seg * 8;
                cp16(sb + P_AHI + (uint32_t)(plane * 10240 + row * PRS + seg * 16), src);
            } else {
                int v = u - 1024;
                int plane = v >> 8, idx = v & 255;
                int row = idx >> 2, seg = idx & 3;
                const __nv_bfloat16* src = (plane ? Wlo : Whi)
                    + (size_t)(bcol + row) * K + k0 + seg * 8;
                cp16(sb + P_BHI + (uint32_t)(plane * 5120 + row * PRS + seg * 16), src);
            }
        }
        cp_commit();
    };

    issue_stage(0);
    for (int kt = 0; kt < KT; kt++) {
        if (kt + 1 < KT) {
            issue_stage(kt + 1);
            asm volatile("cp.async.wait_group 1;");
        } else {
            asm volatile("cp.async.wait_group 0;");
        }
        __syncthreads();
        const uint32_t sb = smu + (uint32_t)((kt & 1) * P_STAGE);
#pragma unroll
        for (int s = 0; s < 2; s++) {
            uint32_t ah[2][4], al[2][4], bh[2][4], bl[2][4];
#pragma unroll
            for (int mi = 0; mi < 2; mi++) {
                ldsm4(ah[mi], sb + P_AHI + a_off + (uint32_t)(mi * 16 * PRS + s * 32));
                ldsm4(al[mi], sb + P_ALO + a_off + (uint32_t)(mi * 16 * PRS + s * 32));
            }
#pragma unroll
            for (int nh = 0; nh < 2; nh++) {
                ldsm4(bh[nh], sb + P_BHI + b_off + (uint32_t)(nh * 16 * PRS + s * 32));
                ldsm4(bl[nh], sb + P_BLO + b_off + (uint32_t)(nh * 16 * PRS + s * 32));
            }
#pragma unroll
            for (int mi = 0; mi < 2; mi++)
#pragma unroll
                for (int nj = 0; nj < 4; nj++) {
                    const uint32_t* bhf = &bh[nj >> 1][(nj & 1) * 2];
                    const uint32_t* blf = &bl[nj >> 1][(nj & 1) * 2];
                    mma_bf16v(acc[mi][nj], ah[mi], bhf);
                    mma_bf16v(acc[mi][nj], ah[mi], blf);
                    mma_bf16v(acc[mi][nj], al[mi], bhf);
                }
        }
        __syncthreads();
    }

    const int gid = lane >> 2, tig = lane & 3;
#pragma unroll
    for (int mi = 0; mi < 2; mi++) {
        const int r0 = brow + wm * 32 + mi * 16 + gid;
#pragma unroll
        for (int nj = 0; nj < 4; nj++) {
            const int col = bcol + wn * 32 + nj * 8 + tig * 2;
            float bx = b0[col] + b1[col];
            float by = b0[col + 1] + b1[col + 1];
            *(float2*)&C[(size_t)r0 * HH + col] =
                make_float2(acc[mi][nj][0] + bx, acc[mi][nj][1] + by);
            *(float2*)&C[(size_t)(r0 + 8) * HH + col] =
                make_float2(acc[mi][nj][2] + bx, acc[mi][nj][3] + by);
        }
    }
}

// ---------------------------------------------------------------------------
// Persistent HMMA recurrent layer (12 independent accumulators, x4 B loads).
// ---------------------------------------------------------------------------
__global__ __launch_bounds__(NTHR, 1) void rnn_layer_tc(
    const float* __restrict__ pre,
    float* __restrict__ hbase,
    const float* __restrict__ Whh)
{
    extern __shared__ char smb[];
    const uint32_t smu = smem_u32(smb);

    const int tid  = threadIdx.x;
    const int wid  = tid >> 5;
    const int lane = tid & 31;
    const int bcol = blockIdx.x * NCOLS;

    // one-time W slice: fp32 -> bf16 hi/lo, [n][k] padded rows
    for (int i = tid; i < NCOLS * HH; i += NTHR) {
        int n = i >> 10;
        int k = i & 1023;
        float v = Whh[(size_t)(bcol + n) * HH + k];
        __nv_bfloat16 hi = __float2bfloat16(v);
        __nv_bfloat16 lo = __float2bfloat16(v - __bfloat162float(hi));
        *(__nv_bfloat16*)(smb + SM_WHI + n * WROWB + k * 2) = hi;
        *(__nv_bfloat16*)(smb + SM_WLO + n * WROWB + k * 2) = lo;
    }
    __syncthreads();

    const int mt = wid >> 1;            // m-tile (16 rows)
    const int nt = wid & 1;             // n-tile (8 cols)

    const int grp = lane >> 3;
    const int rin = lane & 7;
    // A x4 lane offset (16 rows x k16)
    const uint32_t a_lane_off =
        (uint32_t)((mt * 16 + (grp & 1) * 8 + rin) * AROWB + (grp >> 1) * 16);
    // B x4 lane offset: (n0-7, k0/k8/k16/k24) -> frags for 2 consecutive k16
    const uint32_t b4_off =
        (uint32_t)((nt * 8 + rin) * WROWB + grp * 16);

    const size_t row_stride = (size_t)TT * HH;

    for (int t = 0; t < TT; t++) {
        float acc[12][4];
#pragma unroll
        for (int i = 0; i < 12; i++)
#pragma unroll
            for (int q = 0; q < 4; q++) acc[i][q] = 0.f;

        if (t > 0) {
            // ---- stage chunk 0 ----
#pragma unroll
            for (int i = 0; i < 8; i++) {
                int u = tid + i * NTHR;
                int row = u >> 5;
                int ku  = u & 31;
                uint32_t d = smu + SM_A + (uint32_t)(row * AROWB + ku * 16);
                const size_t gsrc = (size_t)row * HH + ku * 8;
                cp16(d,         g_hhi + gsrc);
                cp16(d + A_ONE, g_hlo + gsrc);
            }
            cp_commit();

#pragma unroll
            for (int c = 0; c < 4; c++) {
                if (c < 3) {
                    const uint32_t bb = smu + SM_A + ((c + 1) & 1) * ABUFP;
#pragma unroll
                    for (int i = 0; i < 8; i++) {
                        int u = tid + i * NTHR;
                        int row = u >> 5;
                        int ku  = u & 31;
                        uint32_t d = bb + (uint32_t)(row * AROWB + ku * 16);
                        const size_t gsrc = (size_t)row * HH + (c + 1) * 256 + ku * 8;
                        cp16(d,         g_hhi + gsrc);
                        cp16(d + A_ONE, g_hlo + gsrc);
                    }
                    cp_commit();
                    asm volatile("cp.async.wait_group 1;");
                } else {
                    asm volatile("cp.async.wait_group 0;");
                }
                __syncthreads();

                const uint32_t ahb = smu + SM_A + (c & 1) * ABUFP + a_lane_off;
                const uint32_t alb = ahb + A_ONE;
                const uint32_t bhb = smu + SM_WHI + b4_off + (uint32_t)(c * 512);
                const uint32_t blb = smu + SM_WLO + b4_off + (uint32_t)(c * 512);
#pragma unroll
                for (int p2 = 0; p2 < 8; p2++) {
                    uint32_t bh[4], bl[4];
                    ldsm4(bh, bhb + p2 * 64);
                    ldsm4(bl, blb + p2 * 64);
#pragma unroll
                    for (int e = 0; e < 2; e++) {
                        const int s = p2 * 2 + e;
                        const int q = s & 3;
                        uint32_t ah[4], al[4];
                        ldsm4(ah, ahb + s * 32);
                        ldsm4(al, alb + s * 32);
                        const uint32_t* bhf = &bh[e * 2];
                        const uint32_t* blf = &bl[e * 2];
                        mma_bf16v(acc[q],     ah, bhf);
                        mma_bf16v(acc[4 + q], ah, blf);
                        mma_bf16v(acc[8 + q], al, bhf);
                    }
                }
                __syncthreads();
            }
        }

        // ---- epilogue ----
        {
            float c0 = 0.f, c1 = 0.f, c2 = 0.f, c3 = 0.f;
#pragma unroll
            for (int i = 0; i < 12; i++) {
                c0 += acc[i][0]; c1 += acc[i][1];
                c2 += acc[i][2]; c3 += acc[i][3];
            }

            const int gid = lane >> 2;
            const int tig = lane & 3;
            const int m0 = mt * 16 + gid;
            const int m1 = m0 + 8;
            const int nc = bcol + nt * 8 + tig * 2;

            const size_t o0 = (size_t)m0 * row_stride + (size_t)t * HH + nc;
            const size_t o1 = (size_t)m1 * row_stride + (size_t)t * HH + nc;

            float2 p0 = *(const float2*)&pre[o0];
            float2 p1 = *(const float2*)&pre[o1];
            float h00 = tanhf(p0.x + c0);
            float h01 = tanhf(p0.y + c1);
            float h10 = tanhf(p1.x + c2);
            float h11 = tanhf(p1.y + c3);
            *(float2*)&hbase[o0] = make_float2(h00, h01);
            *(float2*)&hbase[o1] = make_float2(h10, h11);

            __nv_bfloat16 e00 = __float2bfloat16(h00);
            __nv_bfloat16 e01 = __float2bfloat16(h01);
            __nv_bfloat16 e10 = __float2bfloat16(h10);
            __nv_bfloat16 e11 = __float2bfloat16(h11);
            uint32_t hi0 = pack_bf16(h00, h01);
            uint32_t hi1 = pack_bf16(h10, h11);
            float f00 = __bfloat162float(e00);
            float f01 = __bfloat162float(e01);
            float f10 = __bfloat162float(e10);
            float f11 = __bfloat162float(e11);
            uint32_t lo0 = pack_bf16(h00 - f00, h01 - f01);
            uint32_t lo1 = pack_bf16(h10 - f10, h11 - f11);

            *(uint32_t*)&g_hhi[(size_t)m0 * HH + nc] = hi0;
            *(uint32_t*)&g_hhi[(size_t)m1 * HH + nc] = hi1;
            *(uint32_t*)&g_hlo[(size_t)m0 * HH + nc] = lo0;
            *(uint32_t*)&g_hlo[(size_t)m1 * HH + nc] = lo1;
        }

        grid_barrier64();
    }
}

// ---------------------------------------------------------------------------
__global__ void finalize_kernel(float* __restrict__ out)
{
    int i = blockIdx.x * blockDim.x + threadIdx.x;   // over B*H
    if (i >= BB * HH) return;
    int b = i / HH;
    int h = i - b * HH;
    float* hfin = out + (size_t)BB * TT * HH;
    size_t src = (size_t)b * TT * HH + (size_t)(TT - 1) * HH + h;
    hfin[i] = g_buf0[src];
    hfin[(size_t)BB * HH + i] = out[src];
}

// ---------------------------------------------------------------------------

extern "C" void kernel_launch(void* const* d_in, const int* in_sizes, int n_in,
                              void* d_out, int out_size)
{
    const float* x      = (const float*)d_in[0];
    const float* W_ih0  = (const float*)d_in[1];
    const float* W_hh0  = (const float*)d_in[2];
    const float* b_ih0  = (const float*)d_in[3];
    const float* b_hh0  = (const float*)d_in[4];
    const float* W_ih1  = (const float*)d_in[5];
    const float* W_hh1  = (const float*)d_in[6];
    const float* b_ih1  = (const float*)d_in[7];
    const float* b_hh1  = (const float*)d_in[8];
    float* out = (float*)d_out;

    void* p;
    cudaGetSymbolAddress(&p, g_buf0); float* buf0 = (float*)p;
    cudaGetSymbolAddress(&p, g_buf1); float* buf1 = (float*)p;
    cudaGetSymbolAddress(&p, g_ahi);  __nv_bfloat16* ahi = (__nv_bfloat16*)p;
    cudaGetSymbolAddress(&p, g_alo);  __nv_bfloat16* alo = (__nv_bfloat16*)p;
    cudaGetSymbolAddress(&p, g_whi);  __nv_bfloat16* whi = (__nv_bfloat16*)p;
    cudaGetSymbolAddress(&p, g_wlo);  __nv_bfloat16* wlo = (__nv_bfloat16*)p;

    cudaFuncSetAttribute(rnn_layer_tc,
                         cudaFuncAttributeMaxDynamicSharedMemorySize, SM_TOTAL);
    cudaFuncSetAttribute(hmma_pre_gemm,
                         cudaFuncAttributeMaxDynamicSharedMemorySize, P_SMEM);

    // 1) split X and W_ih0 to bf16 hi/lo
    conv_split_kernel<<<1024, 256>>>(x, ahi, alo, BB * TT * DIN);
    conv_split_kernel<<<256, 256>>>(W_ih0, whi, wlo, HH * DIN);

    // 2) pre0 = X @ W_ih0^T + b_ih0 + b_hh0   (HMMA 3-pass)
    {
        dim3 grid(HH / 64, (BB * TT) / 128);
        hmma_pre_gemm<<<grid, 256, P_SMEM>>>(ahi, alo, whi, wlo,
                                             b_ih0, b_hh0, buf0, DIN);
    }

    // 3) layer-0 recurrence (in place over buf0)
    rnn_layer_tc<<<NBLK, NTHR, SM_TOTAL>>>(buf0, buf0, W_hh0);

    // 4) split H0 and W_ih1, then pre1 = H0 @ W_ih1^T + b_ih1 + b_hh1
    conv_split_kernel<<<1024, 256>>>(buf0, ahi, alo, BB * TT * HH);
    conv_split_kernel<<<512, 256>>>(W_ih1, whi, wlo, HH * HH);
    {
        dim3 grid(HH / 64, (BB * TT) / 128);
        hmma_pre_gemm<<<grid, 256, P_SMEM>>>(ahi, alo, whi, wlo,
                                             b_ih1, b_hh1, buf1, HH);
    }

    // 5) layer-1 recurrence (writes h1 into outputs region)
    rnn_layer_tc<<<NBLK, NTHR, SM_TOTAL>>>(buf1, out, W_hh1);

    // 6) h_final
    finalize_kernel<<<(BB * HH + 255) / 256, 256>>>(out);
}

// round 8
// speedup vs baseline: 2.8920x; 1.4550x over previous
#include <cuda_runtime.h>
#include <cuda_bf16.h>
#include <math.h>
#include <stdint.h>

#define BB 64
#define TT 512
#define DIN 512
#define HH 1024

// rnn grid: 32 col-groups x 4 row-groups = 128 blocks
#define NCOLBLK 32
#define NROWGRP 4
#define RNBLK (NCOLBLK * NROWGRP)
#define NCOLS 32     // hidden cols per block
#define NROWS 16     // batch rows per block
#define NTHR 256

// rnn SMEM layout (bytes; 16B-aligned)
#define AROWB 528            // A chunk row stride: 256 bf16 + 8 pad
#define WROWB 2064           // W row stride: 1024 bf16 + 8 pad
#define SM_WHI 0
#define SM_WLO (NCOLS * WROWB)            // 66048
#define SM_A   (2 * NCOLS * WROWB)        // 132096
#define A_ONE  (NROWS * AROWB)            // 8448 (one hi or lo plane)
#define ABUFP  (2 * A_ONE)                // 16896 (hi+lo per buffer)
#define SM_SCR (SM_A + 2 * ABUFP)         // 165888 (fp32 partial-C scratch)
#define SM_TOTAL (SM_SCR + 2048)          // 167936

// Scratch: buf0 holds pre0 then h0 in place; buf1 holds pre1. h1 -> d_out.
__device__ float g_buf0[(size_t)BB * TT * HH];
__device__ float g_buf1[(size_t)BB * TT * HH];
// Current h(t) as bf16 hi/lo split (rewritten every step)
__device__ __nv_bfloat16 g_hhi[(size_t)BB * HH];
__device__ __nv_bfloat16 g_hlo[(size_t)BB * HH];
// bf16 hi/lo split of the big GEMM A operand (X, then H0) and W operand
__device__ __nv_bfloat16 g_ahi[(size_t)BB * TT * HH];
__device__ __nv_bfloat16 g_alo[(size_t)BB * TT * HH];
__device__ __nv_bfloat16 g_whi[(size_t)HH * HH];
__device__ __nv_bfloat16 g_wlo[(size_t)HH * HH];

// Per-row-group grid barriers (32 arrivals each; generation-based)
__device__ unsigned int          g_bar_count[NROWGRP];
__device__ volatile unsigned int g_bar_gen[NROWGRP];

__device__ __forceinline__ void group_barrier(int rg)
{
    __syncthreads();
    __threadfence();
    if (threadIdx.x == 0) {
        unsigned int gen = g_bar_gen[rg];
        unsigned int tkt = atomicAdd(&g_bar_count[rg], 1u);
        if (tkt == NCOLBLK - 1) {
            g_bar_count[rg] = 0;
            __threadfence();
            g_bar_gen[rg] = gen + 1;
        } else {
            while (g_bar_gen[rg] == gen) { __nanosleep(32); }
        }
    }
    __syncthreads();
}

// ---------------------- PTX helpers (sm_80+ features only) ----------------
__device__ __forceinline__ uint32_t smem_u32(const void* p) {
    uint32_t a;
    asm("{ .reg .u64 t; cvta.to.shared.u64 t, %1; cvt.u32.u64 %0, t; }"
        : "=r"(a) : "l"(p));
    return a;
}
__device__ __forceinline__ void cp16(uint32_t dst, const void* src) {
    asm volatile("cp.async.cg.shared.global [%0], [%1], 16;"
                 :: "r"(dst), "l"(src));
}
__device__ __forceinline__ void cp_commit() {
    asm volatile("cp.async.commit_group;");
}
__device__ __forceinline__ void ldsm4(uint32_t* r, uint32_t addr) {
    asm volatile("ldmatrix.sync.aligned.m8n8.x4.shared.b16 {%0,%1,%2,%3}, [%4];"
                 : "=r"(r[0]), "=r"(r[1]), "=r"(r[2]), "=r"(r[3]) : "r"(addr));
}
__device__ __forceinline__ void mma_bf16v(float* c, const uint32_t* a,
                                          const uint32_t* b) {
    asm volatile(
        "mma.sync.aligned.m16n8k16.row.col.f32.bf16.bf16.f32 "
        "{%0,%1,%2,%3}, {%4,%5,%6,%7}, {%8,%9}, {%0,%1,%2,%3};"
        : "+f"(c[0]), "+f"(c[1]), "+f"(c[2]), "+f"(c[3])
        : "r"(a[0]), "r"(a[1]), "r"(a[2]), "r"(a[3]), "r"(b[0]), "r"(b[1]));
}
__device__ __forceinline__ uint32_t pack_bf16(float x, float y) {
    __nv_bfloat162 v = __floats2bfloat162_rn(x, y);
    return *(uint32_t*)&v;
}

// ---------------------------------------------------------------------------
// fp32 -> bf16 hi/lo split (elementwise, grid-stride, n % 4 == 0)
// ---------------------------------------------------------------------------
__global__ void conv_split_kernel(const float* __restrict__ in,
                                  __nv_bfloat16* __restrict__ hi,
                                  __nv_bfloat16* __restrict__ lo, int n)
{
    int stride = gridDim.x * blockDim.x * 4;
    for (int i = (blockIdx.x * blockDim.x + threadIdx.x) * 4; i < n; i += stride) {
        float4 f = *(const float4*)&in[i];
        __nv_bfloat16 hx = __float2bfloat16(f.x);
        __nv_bfloat16 hy = __float2bfloat16(f.y);
        __nv_bfloat16 hz = __float2bfloat16(f.z);
        __nv_bfloat16 hw = __float2bfloat16(f.w);
        uint32_t h0 = pack_bf16(f.x, f.y);
        uint32_t h1 = pack_bf16(f.z, f.w);
        uint32_t l0 = pack_bf16(f.x - __bfloat162float(hx), f.y - __bfloat162float(hy));
        uint32_t l1 = pack_bf16(f.z - __bfloat162float(hz), f.w - __bfloat162float(hw));
        *(uint2*)&hi[i] = make_uint2(h0, h1);
        *(uint2*)&lo[i] = make_uint2(l0, l1);
    }
}

// ---------------------------------------------------------------------------
// HMMA pre-GEMM (R6 version, known good): C = Ah@(Wh+Wl)^T + Al@Wh^T + bias
// ---------------------------------------------------------------------------
#define PRS 80
#define P_AHI 0
#define P_ALO 10240
#define P_BHI 20480
#define P_BLO 25600
#define P_STAGE 30720
#define P_SMEM (2 * P_STAGE)

__global__ __launch_bounds__(256) void hmma_pre_gemm(
    const __nv_bfloat16* __restrict__ Ahi,
    const __nv_bfloat16* __restrict__ Alo,
    const __nv_bfloat16* __restrict__ Whi,
    const __nv_bfloat16* __restrict__ Wlo,
    const float* __restrict__ b0,
    const float* __restrict__ b1,
    float* __restrict__ C,
    int K)
{
    extern __shared__ char smb[];
    const uint32_t smu = smem_u32(smb);
    const int tid  = threadIdx.x;
    const int lane = tid & 31;
    const int wid  = tid >> 5;
    const int wm   = wid >> 1;
    const int wn   = wid & 1;
    const int brow = blockIdx.y * 128;
    const int bcol = blockIdx.x * 64;

    float acc[2][4][4];
#pragma unroll
    for (int mi = 0; mi < 2; mi++)
#pragma unroll
        for (int nj = 0; nj < 4; nj++)
#pragma unroll
            for (int q = 0; q < 4; q++) acc[mi][nj][q] = 0.f;

    const int grp = lane >> 3, rin = lane & 7;
    const uint32_t a_off = (uint32_t)((wm * 32 + (grp & 1) * 8 + rin) * PRS
                                      + (grp >> 1) * 16);
    const uint32_t b_off = (uint32_t)((wn * 32 + (grp >> 1) * 8 + rin) * PRS
                                      + (grp & 1) * 16);

    const int KT = K >> 5;

    auto issue_stage = [&](int kt) {
        const uint32_t sb = smu + (uint32_t)((kt & 1) * P_STAGE);
        const int k0 = kt * 32;
#pragma unroll
        for (int i = 0; i < 6; i++) {
            int u = tid + i * 256;
            if (u < 1024) {
                int plane = u >> 9, idx = u & 511;
                int row = idx >> 2, seg = idx & 3;
                const __nv_bfloat16* src = (plane ? Alo : Ahi)
                    + (size_t)(brow + row) * K + k0 + seg * 8;
                cp16(sb + P_AHI + (uint32_t)(plane * 10240 + row * PRS + seg * 16), src);
            } else {
                int v = u - 1024;
                int plane = v >> 8, idx = v & 255;
                int row = idx >> 2, seg = idx & 3;
                const __nv_bfloat16* src = (plane ? Wlo : Whi)
                    + (size_t)(bcol + row) * K + k0 + seg * 8;
                cp16(sb + P_BHI + (uint32_t)(plane * 5120 + row * PRS + seg * 16), src);
            }
        }
        cp_commit();
    };

    issue_stage(0);
    for (int kt = 0; kt < KT; kt++) {
        if (kt + 1 < KT) {
            issue_stage(kt + 1);
            asm volatile("cp.async.wait_group 1;");
        } else {
            asm volatile("cp.async.wait_group 0;");
        }
        __syncthreads();
        const uint32_t sb = smu + (uint32_t)((kt & 1) * P_STAGE);
#pragma unroll
        for (int s = 0; s < 2; s++) {
            uint32_t ah[2][4], al[2][4], bh[2][4], bl[2][4];
#pragma unroll
            for (int mi = 0; mi < 2; mi++) {
                ldsm4(ah[mi], sb + P_AHI + a_off + (uint32_t)(mi * 16 * PRS + s * 32));
                ldsm4(al[mi], sb + P_ALO + a_off + (uint32_t)(mi * 16 * PRS + s * 32));
            }
#pragma unroll
            for (int nh = 0; nh < 2; nh++) {
                ldsm4(bh[nh], sb + P_BHI + b_off + (uint32_t)(nh * 16 * PRS + s * 32));
                ldsm4(bl[nh], sb + P_BLO + b_off + (uint32_t)(nh * 16 * PRS + s * 32));
            }
#pragma unroll
            for (int mi = 0; mi < 2; mi++)
#pragma unroll
                for (int nj = 0; nj < 4; nj++) {
                    const uint32_t* bhf = &bh[nj >> 1][(nj & 1) * 2];
                    const uint32_t* blf = &bl[nj >> 1][(nj & 1) * 2];
                    mma_bf16v(acc[mi][nj], ah[mi], bhf);
                    mma_bf16v(acc[mi][nj], ah[mi], blf);
                    mma_bf16v(acc[mi][nj], al[mi], bhf);
                }
        }
        __syncthreads();
    }

    const int gid = lane >> 2, tig = lane & 3;
#pragma unroll
    for (int mi = 0; mi < 2; mi++) {
        const int r0 = brow + wm * 32 + mi * 16 + gid;
#pragma unroll
        for (int nj = 0; nj < 4; nj++) {
            const int col = bcol + wn * 32 + nj * 8 + tig * 2;
            float bx = b0[col] + b1[col];
            float by = b0[col + 1] + b1[col + 1];
            *(float2*)&C[(size_t)r0 * HH + col] =
                make_float2(acc[mi][nj][0] + bx, acc[mi][nj][1] + by);
            *(float2*)&C[(size_t)(r0 + 8) * HH + col] =
                make_float2(acc[mi][nj][2] + bx, acc[mi][nj][3] + by);
        }
    }
}

// ---------------------------------------------------------------------------
// Persistent HMMA recurrent layer, 2-D split.
// 128 blocks = 32 col-groups x 4 row-groups; block tile 16 rows x 32 cols.
// W slice (32 cols) bf16 hi/lo resident in SMEM. Per step: stage only this
// row-group's 16 h-rows (64 KB) in 4 pipelined chunks of k256.
// 8 warps = 4 n-tiles x 2 k-groups; k-group partials merged via SMEM scratch.
// ---------------------------------------------------------------------------
__global__ __launch_bounds__(NTHR, 1) void rnn_layer_tc(
    const float* __restrict__ pre,
    float* __restrict__ hbase,
    const float* __restrict__ Whh)
{
    extern __shared__ char smb[];
    const uint32_t smu = smem_u32(smb);

    const int tid  = threadIdx.x;
    const int wid  = tid >> 5;
    const int lane = tid & 31;
    const int cb   = blockIdx.x & (NCOLBLK - 1);
    const int rg   = blockIdx.x >> 5;            // row group 0..3
    const int bcol = cb * NCOLS;
    const int brow = rg * NROWS;

    // one-time W slice: fp32 -> bf16 hi/lo, [n][k] padded rows
    for (int i = tid; i < NCOLS * HH; i += NTHR) {
        int n = i >> 10;
        int k = i & 1023;
        float v = Whh[(size_t)(bcol + n) * HH + k];
        __nv_bfloat16 hi = __float2bfloat16(v);
        __nv_bfloat16 lo = __float2bfloat16(v - __bfloat162float(hi));
        *(__nv_bfloat16*)(smb + SM_WHI + n * WROWB + k * 2) = hi;
        *(__nv_bfloat16*)(smb + SM_WLO + n * WROWB + k * 2) = lo;
    }
    __syncthreads();

    const int nt = wid & 3;             // n-tile (8 cols)
    const int kg = wid >> 2;            // k-group (half of each chunk)

    const int grp = lane >> 3;
    const int rin = lane & 7;
    // A x4 lane offset (16 rows x k16)
    const uint32_t a_lane_off =
        (uint32_t)(((grp & 1) * 8 + rin) * AROWB + (grp >> 1) * 16);
    // B x4 lane offset: (n8, k32) group
    const uint32_t b4_off =
        (uint32_t)((nt * 8 + rin) * WROWB + grp * 16);

    const size_t row_stride = (size_t)TT * HH;
    const uint32_t scr = smu + SM_SCR + (uint32_t)((nt * 32 + lane) * 16);

    for (int t = 0; t < TT; t++) {
        float acc[6][4];
#pragma unroll
        for (int i = 0; i < 6; i++)
#pragma unroll
            for (int q = 0; q < 4; q++) acc[i][q] = 0.f;

        if (t > 0) {
            // ---- stage chunk 0 (16 rows x 256 k, hi+lo = 16 KB) ----
#pragma unroll
            for (int i = 0; i < 4; i++) {
                int u = tid + i * NTHR;           // 0..1023
                int plane = u >> 9;
                int idx = u & 511;
                int row = idx >> 5;
                int ku  = idx & 31;
                uint32_t d = smu + SM_A + (uint32_t)(plane * A_ONE + row * AROWB + ku * 16);
                const __nv_bfloat16* src = (plane ? g_hlo : g_hhi)
                    + (size_t)(brow + row) * HH + ku * 8;
                cp16(d, src);
            }
            cp_commit();

#pragma unroll
            for (int c = 0; c < 4; c++) {
                if (c < 3) {
                    const uint32_t bb = smu + SM_A + ((c + 1) & 1) * ABUFP;
#pragma unroll
                    for (int i = 0; i < 4; i++) {
                        int u = tid + i * NTHR;
                        int plane = u >> 9;
                        int idx = u & 511;
                        int row = idx >> 5;
                        int ku  = idx & 31;
                        uint32_t d = bb + (uint32_t)(plane * A_ONE + row * AROWB + ku * 16);
                        const __nv_bfloat16* src = (plane ? g_hlo : g_hhi)
                            + (size_t)(brow + row) * HH + (c + 1) * 256 + ku * 8;
                        cp16(d, src);
                    }
                    cp_commit();
                    asm volatile("cp.async.wait_group 1;");
                } else {
                    asm volatile("cp.async.wait_group 0;");
                }
                __syncthreads();

                // k-group kg covers k-steps [kg*8, kg*8+8) of this chunk
                const uint32_t ahb = smu + SM_A + (c & 1) * ABUFP + a_lane_off
                                   + (uint32_t)(kg * 256);
                const uint32_t alb = ahb + A_ONE;
                const uint32_t bhb = smu + SM_WHI + b4_off
                                   + (uint32_t)(c * 512 + kg * 256);
                const uint32_t blb = smu + SM_WLO + b4_off
                                   + (uint32_t)(c * 512 + kg * 256);
#pragma unroll
                for (int p2 = 0; p2 < 4; p2++) {      // k32 groups
                    uint32_t bh[4], bl[4];
                    ldsm4(bh, bhb + p2 * 64);
                    ldsm4(bl, blb + p2 * 64);
#pragma unroll
                    for (int e = 0; e < 2; e++) {
                        const int s = p2 * 2 + e;
                        uint32_t ah[4], al[4];
                        ldsm4(ah, ahb + s * 32);
                        ldsm4(al, alb + s * 32);
                        const uint32_t* bhf = &bh[e * 2];
                        const uint32_t* blf = &bl[e * 2];
                        mma_bf16v(acc[(s & 1) * 3 + 0], ah, bhf);
                        mma_bf16v(acc[(s & 1) * 3 + 1], ah, blf);
                        mma_bf16v(acc[(s & 1) * 3 + 2], al, bhf);
                    }
                }
                __syncthreads();
            }
        }

        // ---- merge k-group partials + epilogue ----
        float c0 = 0.f, c1 = 0.f, c2 = 0.f, c3 = 0.f;
#pragma unroll
        for (int i = 0; i < 6; i++) {
            c0 += acc[i][0]; c1 += acc[i][1];
            c2 += acc[i][2]; c3 += acc[i][3];
        }

        if (t > 0) {
            if (kg == 1) {
                asm volatile("st.shared.v4.f32 [%0], {%1,%2,%3,%4};"
                             :: "r"(scr), "f"(c0), "f"(c1), "f"(c2), "f"(c3)
                             : "memory");
            }
            __syncthreads();
        }

        if (kg == 0) {
            if (t > 0) {
                float s0, s1, s2, s3;
                asm volatile("ld.shared.v4.f32 {%0,%1,%2,%3}, [%4];"
                             : "=f"(s0), "=f"(s1), "=f"(s2), "=f"(s3) : "r"(scr));
                c0 += s0; c1 += s1; c2 += s2; c3 += s3;
            }

            const int gid = lane >> 2;
            const int tig = lane & 3;
            const int m0 = brow + gid;
            const int m1 = m0 + 8;
            const int nc = bcol + nt * 8 + tig * 2;

            const size_t o0 = (size_t)m0 * row_stride + (size_t)t * HH + nc;
            const size_t o1 = (size_t)m1 * row_stride + (size_t)t * HH + nc;

            float2 p0 = *(const float2*)&pre[o0];
            float2 p1 = *(const float2*)&pre[o1];
            float h00 = tanhf(p0.x + c0);
            float h01 = tanhf(p0.y + c1);
            float h10 = tanhf(p1.x + c2);
            float h11 = tanhf(p1.y + c3);
            *(float2*)&hbase[o0] = make_float2(h00, h01);
            *(float2*)&hbase[o1] = make_float2(h10, h11);

            __nv_bfloat16 e00 = __float2bfloat16(h00);
            __nv_bfloat16 e01 = __float2bfloat16(h01);
            __nv_bfloat16 e10 = __float2bfloat16(h10);
            __nv_bfloat16 e11 = __float2bfloat16(h11);
            uint32_t hi0 = pack_bf16(h00, h01);
            uint32_t hi1 = pack_bf16(h10, h11);
            uint32_t lo0 = pack_bf16(h00 - __bfloat162float(e00),
                                     h01 - __bfloat162float(e01));
            uint32_t lo1 = pack_bf16(h10 - __bfloat162float(e10),
                                     h11 - __bfloat162float(e11));

            *(uint32_t*)&g_hhi[(size_t)m0 * HH + nc] = hi0;
            *(uint32_t*)&g_hhi[(size_t)m1 * HH + nc] = hi1;
            *(uint32_t*)&g_hlo[(size_t)m0 * HH + nc] = lo0;
            *(uint32_t*)&g_hlo[(size_t)m1 * HH + nc] = lo1;
        }

        group_barrier(rg);
    }
}

// ---------------------------------------------------------------------------
__global__ void finalize_kernel(float* __restrict__ out)
{
    int i = blockIdx.x * blockDim.x + threadIdx.x;   // over B*H
    if (i >= BB * HH) return;
    int b = i / HH;
    int h = i - b * HH;
    float* hfin = out + (size_t)BB * TT * HH;
    size_t src = (size_t)b * TT * HH + (size_t)(TT - 1) * HH + h;
    hfin[i] = g_buf0[src];
    hfin[(size_t)BB * HH + i] = out[src];
}

// ---------------------------------------------------------------------------

extern "C" void kernel_launch(void* const* d_in, const int* in_sizes, int n_in,
                              void* d_out, int out_size)
{
    const float* x      = (const float*)d_in[0];
    const float* W_ih0  = (const float*)d_in[1];
    const float* W_hh0  = (const float*)d_in[2];
    const float* b_ih0  = (const float*)d_in[3];
    const float* b_hh0  = (const float*)d_in[4];
    const float* W_ih1  = (const float*)d_in[5];
    const float* W_hh1  = (const float*)d_in[6];
    const float* b_ih1  = (const float*)d_in[7];
    const float* b_hh1  = (const float*)d_in[8];
    float* out = (float*)d_out;

    void* p;
    cudaGetSymbolAddress(&p, g_buf0); float* buf0 = (float*)p;
    cudaGetSymbolAddress(&p, g_buf1); float* buf1 = (float*)p;
    cudaGetSymbolAddress(&p, g_ahi);  __nv_bfloat16* ahi = (__nv_bfloat16*)p;
    cudaGetSymbolAddress(&p, g_alo);  __nv_bfloat16* alo = (__nv_bfloat16*)p;
    cudaGetSymbolAddress(&p, g_whi);  __nv_bfloat16* whi = (__nv_bfloat16*)p;
    cudaGetSymbolAddress(&p, g_wlo);  __nv_bfloat16* wlo = (__nv_bfloat16*)p;

    cudaFuncSetAttribute(rnn_layer_tc,
                         cudaFuncAttributeMaxDynamicSharedMemorySize, SM_TOTAL);
    cudaFuncSetAttribute(hmma_pre_gemm,
                         cudaFuncAttributeMaxDynamicSharedMemorySize, P_SMEM);

    // 1) split X and W_ih0 to bf16 hi/lo
    conv_split_kernel<<<1024, 256>>>(x, ahi, alo, BB * TT * DIN);
    conv_split_kernel<<<256, 256>>>(W_ih0, whi, wlo, HH * DIN);

    // 2) pre0 = X @ W_ih0^T + b_ih0 + b_hh0
    {
        dim3 grid(HH / 64, (BB * TT) / 128);
        hmma_pre_gemm<<<grid, 256, P_SMEM>>>(ahi, alo, whi, wlo,
                                             b_ih0, b_hh0, buf0, DIN);
    }

    // 3) layer-0 recurrence (in place over buf0)
    rnn_layer_tc<<<RNBLK, NTHR, SM_TOTAL>>>(buf0, buf0, W_hh0);

    // 4) split H0 and W_ih1, then pre1 = H0 @ W_ih1^T + b_ih1 + b_hh1
    conv_split_kernel<<<1024, 256>>>(buf0, ahi, alo, BB * TT * HH);
    conv_split_kernel<<<512, 256>>>(W_ih1, whi, wlo, HH * HH);
    {
        dim3 grid(HH / 64, (BB * TT) / 128);
        hmma_pre_gemm<<<grid, 256, P_SMEM>>>(ahi, alo, whi, wlo,
                                             b_ih1, b_hh1, buf1, HH);
    }

    // 5) layer-1 recurrence (writes h1 into outputs region)
    rnn_layer_tc<<<RNBLK, NTHR, SM_TOTAL>>>(buf1, out, W_hh1);

    // 6) h_final
    finalize_kernel<<<(BB * HH + 255) / 256, 256>>>(out);
}

// round 9
// speedup vs baseline: 3.2293x; 1.1166x over previous
#include <cuda_runtime.h>
#include <cuda_bf16.h>
#include <math.h>
#include <stdint.h>

#define BB 64
#define TT 512
#define DIN 512
#define HH 1024

// rnn grid: 32 col-groups x 4 row-groups = 128 blocks
#define NCOLBLK 32
#define NROWGRP 4
#define RNBLK (NCOLBLK * NROWGRP)
#define NCOLS 32     // hidden cols per block
#define NROWS 16     // batch rows per block
#define NTHR 256

// rnn SMEM layout (bytes; 16B-aligned)
#define WROWB 2064                 // W row stride: 1024 bf16 + 8 pad
#define CROWB 1040                 // A chunk row stride: 512 bf16 + 8 pad
#define CPLANE (NROWS * CROWB)     // 16640 (one hi or lo plane of a chunk)
#define CBUF (2 * CPLANE)          // 33280 (hi+lo)
#define SM_WHI 0
#define SM_WLO (NCOLS * WROWB)     // 66048
#define SM_A0  (2 * NCOLS * WROWB) // 132096
#define SM_A1  (SM_A0 + CBUF)      // 165376
#define SM_PRE (SM_A1 + CBUF)      // 198656 (16x32 fp32 pre tile)
#define SM_SCR (SM_PRE + 2048)     // 200704 (fp32 partial-C scratch)
#define SM_TOTAL (SM_SCR + 2048)   // 202752

// Scratch: buf0 holds pre0 then h0 in place; buf1 holds pre1. h1 -> d_out.
__device__ float g_buf0[(size_t)BB * TT * HH];
__device__ float g_buf1[(size_t)BB * TT * HH];
// Current h(t) as bf16 hi/lo split (rewritten every step)
__device__ __nv_bfloat16 g_hhi[(size_t)BB * HH];
__device__ __nv_bfloat16 g_hlo[(size_t)BB * HH];
// bf16 hi/lo split of the big GEMM A operand (X, then H0) and W operand
__device__ __nv_bfloat16 g_ahi[(size_t)BB * TT * HH];
__device__ __nv_bfloat16 g_alo[(size_t)BB * TT * HH];
__device__ __nv_bfloat16 g_whi[(size_t)HH * HH];
__device__ __nv_bfloat16 g_wlo[(size_t)HH * HH];

// Per-row-group grid barriers (32 arrivals each; generation-based)
__device__ unsigned int          g_bar_count[NROWGRP];
__device__ volatile unsigned int g_bar_gen[NROWGRP];

// ---------------------- PTX helpers (sm_80+ features only) ----------------
__device__ __forceinline__ uint32_t smem_u32(const void* p) {
    uint32_t a;
    asm("{ .reg .u64 t; cvta.to.shared.u64 t, %1; cvt.u32.u64 %0, t; }"
        : "=r"(a) : "l"(p));
    return a;
}
__device__ __forceinline__ void cp16(uint32_t dst, const void* src) {
    asm volatile("cp.async.cg.shared.global [%0], [%1], 16;"
                 :: "r"(dst), "l"(src));
}
__device__ __forceinline__ void cp_commit() {
    asm volatile("cp.async.commit_group;");
}
__device__ __forceinline__ void ldsm4(uint32_t* r, uint32_t addr) {
    asm volatile("ldmatrix.sync.aligned.m8n8.x4.shared.b16 {%0,%1,%2,%3}, [%4];"
                 : "=r"(r[0]), "=r"(r[1]), "=r"(r[2]), "=r"(r[3]) : "r"(addr));
}
__device__ __forceinline__ void mma_bf16v(float* c, const uint32_t* a,
                                          const uint32_t* b) {
    asm volatile(
        "mma.sync.aligned.m16n8k16.row.col.f32.bf16.bf16.f32 "
        "{%0,%1,%2,%3}, {%4,%5,%6,%7}, {%8,%9}, {%0,%1,%2,%3};"
        : "+f"(c[0]), "+f"(c[1]), "+f"(c[2]), "+f"(c[3])
        : "r"(a[0]), "r"(a[1]), "r"(a[2]), "r"(a[3]), "r"(b[0]), "r"(b[1]));
}
__device__ __forceinline__ uint32_t pack_bf16(float x, float y) {
    __nv_bfloat162 v = __floats2bfloat162_rn(x, y);
    return *(uint32_t*)&v;
}

// ---------------------------------------------------------------------------
// fp32 -> bf16 hi/lo split (elementwise, grid-stride, n % 4 == 0)
// ---------------------------------------------------------------------------
__global__ void conv_split_kernel(const float* __restrict__ in,
                                  __nv_bfloat16* __restrict__ hi,
                                  __nv_bfloat16* __restrict__ lo, int n)
{
    int stride = gridDim.x * blockDim.x * 4;
    for (int i = (blockIdx.x * blockDim.x + threadIdx.x) * 4; i < n; i += stride) {
        float4 f = *(const float4*)&in[i];
        __nv_bfloat16 hx = __float2bfloat16(f.x);
        __nv_bfloat16 hy = __float2bfloat16(f.y);
        __nv_bfloat16 hz = __float2bfloat16(f.z);
        __nv_bfloat16 hw = __float2bfloat16(f.w);
        uint32_t h0 = pack_bf16(f.x, f.y);
        uint32_t h1 = pack_bf16(f.z, f.w);
        uint32_t l0 = pack_bf16(f.x - __bfloat162float(hx), f.y - __bfloat162float(hy));
        uint32_t l1 = pack_bf16(f.z - __bfloat162float(hz), f.w - __bfloat162float(hw));
        *(uint2*)&hi[i] = make_uint2(h0, h1);
        *(uint2*)&lo[i] = make_uint2(l0, l1);
    }
}

// ---------------------------------------------------------------------------
// HMMA pre-GEMM (known good): C = Ah@(Wh+Wl)^T + Al@Wh^T + bias
// ---------------------------------------------------------------------------
#define PRS 80
#define P_AHI 0
#define P_ALO 10240
#define P_BHI 20480
#define P_BLO 25600
#define P_STAGE 30720
#define P_SMEM (2 * P_STAGE)

__global__ __launch_bounds__(256) void hmma_pre_gemm(
    const __nv_bfloat16* __restrict__ Ahi,
    const __nv_bfloat16* __restrict__ Alo,
    const __nv_bfloat16* __restrict__ Whi,
    const __nv_bfloat16* __restrict__ Wlo,
    const float* __restrict__ b0,
    const float* __restrict__ b1,
    float* __restrict__ C,
    int K)
{
    extern __shared__ char smb[];
    const uint32_t smu = smem_u32(smb);
    const int tid  = threadIdx.x;
    const int lane = tid & 31;
    const int wid  = tid >> 5;
    const int wm   = wid >> 1;
    const int wn   = wid & 1;
    const int brow = blockIdx.y * 128;
    const int bcol = blockIdx.x * 64;

    float acc[2][4][4];
#pragma unroll
    for (int mi = 0; mi < 2; mi++)
#pragma unroll
        for (int nj = 0; nj < 4; nj++)
#pragma unroll
            for (int q = 0; q < 4; q++) acc[mi][nj][q] = 0.f;

    const int grp = lane >> 3, rin = lane & 7;
    const uint32_t a_off = (uint32_t)((wm * 32 + (grp & 1) * 8 + rin) * PRS
                                      + (grp >> 1) * 16);
    const uint32_t b_off = (uint32_t)((wn * 32 + (grp >> 1) * 8 + rin) * PRS
                                      + (grp & 1) * 16);

    const int KT = K >> 5;

    auto issue_stage = [&](int kt) {
        const uint32_t sb = smu + (uint32_t)((kt & 1) * P_STAGE);
        const int k0 = kt * 32;
#pragma unroll
        for (int i = 0; i < 6; i++) {
            int u = tid + i * 256;
            if (u < 1024) {
                int plane = u >> 9, idx = u & 511;
                int row = idx >> 2, seg = idx & 3;
                const __nv_bfloat16* src = (plane ? Alo : Ahi)
                    + (size_t)(brow + row) * K + k0 + seg * 8;
                cp16(sb + P_AHI + (uint32_t)(plane * 10240 + row * PRS + seg * 16), src);
            } else {
                int v = u - 1024;
                int plane = v >> 8, idx = v & 255;
                int row = idx >> 2, seg = idx & 3;
                const __nv_bfloat16* src = (plane ? Wlo : Whi)
                    + (size_t)(bcol + row) * K + k0 + seg * 8;
                cp16(sb + P_BHI + (uint32_t)(plane * 5120 + row * PRS + seg * 16), src);
            }
        }
        cp_commit();
    };

    issue_stage(0);
    for (int kt = 0; kt < KT; kt++) {
        if (kt + 1 < KT) {
            issue_stage(kt + 1);
            asm volatile("cp.async.wait_group 1;");
        } else {
            asm volatile("cp.async.wait_group 0;");
        }
        __syncthreads();
        const uint32_t sb = smu + (uint32_t)((kt & 1) * P_STAGE);
#pragma unroll
        for (int s = 0; s < 2; s++) {
            uint32_t ah[2][4], al[2][4], bh[2][4], bl[2][4];
#pragma unroll
            for (int mi = 0; mi < 2; mi++) {
                ldsm4(ah[mi], sb + P_AHI + a_off + (uint32_t)(mi * 16 * PRS + s * 32));
                ldsm4(al[mi], sb + P_ALO + a_off + (uint32_t)(mi * 16 * PRS + s * 32));
            }
#pragma unroll
            for (int nh = 0; nh < 2; nh++) {
                ldsm4(bh[nh], sb + P_BHI + b_off + (uint32_t)(nh * 16 * PRS + s * 32));
                ldsm4(bl[nh], sb + P_BLO + b_off + (uint32_t)(nh * 16 * PRS + s * 32));
            }
#pragma unroll
            for (int mi = 0; mi < 2; mi++)
#pragma unroll
                for (int nj = 0; nj < 4; nj++) {
                    const uint32_t* bhf = &bh[nj >> 1][(nj & 1) * 2];
                    const uint32_t* blf = &bl[nj >> 1][(nj & 1) * 2];
                    mma_bf16v(acc[mi][nj], ah[mi], bhf);
                    mma_bf16v(acc[mi][nj], ah[mi], blf);
                    mma_bf16v(acc[mi][nj], al[mi], bhf);
                }
        }
        __syncthreads();
    }

    const int gid = lane >> 2, tig = lane & 3;
#pragma unroll
    for (int mi = 0; mi < 2; mi++) {
        const int r0 = brow + wm * 32 + mi * 16 + gid;
#pragma unroll
        for (int nj = 0; nj < 4; nj++) {
            const int col = bcol + wn * 32 + nj * 8 + tig * 2;
            float bx = b0[col] + b1[col];
            float by = b0[col + 1] + b1[col + 1];
            *(float2*)&C[(size_t)r0 * HH + col] =
                make_float2(acc[mi][nj][0] + bx, acc[mi][nj][1] + by);
            *(float2*)&C[(size_t)(r0 + 8) * HH + col] =
                make_float2(acc[mi][nj][2] + bx, acc[mi][nj][3] + by);
        }
    }
}

// ---------------------------------------------------------------------------
// Persistent HMMA recurrent layer, 2-D split, tail-optimized.
// 128 blocks = 32 col-groups x 4 row-groups; block tile 16 rows x 32 cols.
// Per step: prefetch pre tile (cp.async), stage h(t-1) in 2 k512 chunks,
// 3-pass bf16 hi/lo MMA, epilogue with early barrier arrival.
// ---------------------------------------------------------------------------
__global__ __launch_bounds__(NTHR, 1) void rnn_layer_tc(
    const float* __restrict__ pre,
    float* __restrict__ hbase,
    const float* __restrict__ Whh)
{
    extern __shared__ char smb[];
    const uint32_t smu = smem_u32(smb);

    const int tid  = threadIdx.x;
    const int wid  = tid >> 5;
    const int lane = tid & 31;
    const int cb   = blockIdx.x & (NCOLBLK - 1);
    const int rg   = blockIdx.x >> 5;            // row group 0..3
    const int bcol = cb * NCOLS;
    const int brow = rg * NROWS;

    // one-time W slice: fp32 -> bf16 hi/lo, [n][k] padded rows
    for (int i = tid; i < NCOLS * HH; i += NTHR) {
        int n = i >> 10;
        int k = i & 1023;
        float v = Whh[(size_t)(bcol + n) * HH + k];
        __nv_bfloat16 hi = __float2bfloat16(v);
        __nv_bfloat16 lo = __float2bfloat16(v - __bfloat162float(hi));
        *(__nv_bfloat16*)(smb + SM_WHI + n * WROWB + k * 2) = hi;
        *(__nv_bfloat16*)(smb + SM_WLO + n * WROWB + k * 2) = lo;
    }
    __syncthreads();

    const int nt = wid & 3;             // n-tile (8 cols)
    const int kg = wid >> 2;            // k-group (half of each chunk)

    const int grp = lane >> 3;
    const int rin = lane & 7;
    // A x4 lane offset (16 rows x k16) within a chunk plane
    const uint32_t a_lane_off =
        (uint32_t)(((grp & 1) * 8 + rin) * CROWB + (grp >> 1) * 16);
    // B x4 lane offset: (n8, k32) group
    const uint32_t b4_off =
        (uint32_t)((nt * 8 + rin) * WROWB + grp * 16);

    const size_t row_stride = (size_t)TT * HH;
    const uint32_t scr = smu + SM_SCR + (uint32_t)((nt * 32 + lane) * 16);

    for (int t = 0; t < TT; t++) {
        float acc[6][4];
#pragma unroll
        for (int i = 0; i < 6; i++)
#pragma unroll
            for (int q = 0; q < 4; q++) acc[i][q] = 0.f;

        if (t > 0) {
            // ---- stage chunk 0 (k 0..511, hi+lo) : group A ----
#pragma unroll
            for (int i = 0; i < 8; i++) {
                int u = tid + i * NTHR;           // 0..2047
                int plane = u >> 10;
                int idx = u & 1023;
                int row = idx >> 6;
                int ku  = idx & 63;
                uint32_t d = smu + SM_A0 + (uint32_t)(plane * CPLANE + row * CROWB + ku * 16);
                const __nv_bfloat16* src = (plane ? g_hlo : g_hhi)
                    + (size_t)(brow + row) * HH + ku * 8;
                cp16(d, src);
            }
            cp_commit();

            // ---- stage chunk 1 (k 512..1023) + pre tile : group B ----
#pragma unroll
            for (int i = 0; i < 8; i++) {
                int u = tid + i * NTHR;
                int plane = u >> 10;
                int idx = u & 1023;
                int row = idx >> 6;
                int ku  = idx & 63;
                uint32_t d = smu + SM_A1 + (uint32_t)(plane * CPLANE + row * CROWB + ku * 16);
                const __nv_bfloat16* src = (plane ? g_hlo : g_hhi)
                    + (size_t)(brow + row) * HH + 512 + ku * 8;
                cp16(d, src);
            }
            if (tid < 128) {
                int row = tid >> 3, q = tid & 7;
                cp16(smu + SM_PRE + (uint32_t)(row * 128 + q * 16),
                     &pre[(size_t)(brow + row) * row_stride + (size_t)t * HH
                          + bcol + q * 4]);
            }
            cp_commit();

            // ---- MMA chunk 0, then chunk 1 ----
            asm volatile("cp.async.wait_group 1;");
            __syncthreads();
#pragma unroll
            for (int c = 0; c < 2; c++) {
                if (c == 1) {
                    asm volatile("cp.async.wait_group 0;");
                    __syncthreads();
                }
                const uint32_t ab = smu + (c ? SM_A1 : SM_A0) + a_lane_off
                                  + (uint32_t)(kg * 512);
                const uint32_t bb_hi = smu + SM_WHI + b4_off
                                     + (uint32_t)(c * 1024 + kg * 512);
                const uint32_t bb_lo = smu + SM_WLO + b4_off
                                     + (uint32_t)(c * 1024 + kg * 512);
#pragma unroll
                for (int p2 = 0; p2 < 8; p2++) {      // k32 groups
                    uint32_t bh[4], bl[4];
                    ldsm4(bh, bb_hi + p2 * 64);
                    ldsm4(bl, bb_lo + p2 * 64);
#pragma unroll
                    for (int e = 0; e < 2; e++) {
                        const int s = p2 * 2 + e;
                        uint32_t ah[4], al[4];
                        ldsm4(ah, ab + s * 32);
                        ldsm4(al, ab + CPLANE + s * 32);
                        const uint32_t* bhf = &bh[e * 2];
                        const uint32_t* blf = &bl[e * 2];
                        mma_bf16v(acc[(s & 1) * 3 + 0], ah, bhf);
                        mma_bf16v(acc[(s & 1) * 3 + 1], ah, blf);
                        mma_bf16v(acc[(s & 1) * 3 + 2], al, bhf);
                    }
                }
            }
        } else {
            // t == 0: just prefetch the pre tile
            if (tid < 128) {
                int row = tid >> 3, q = tid & 7;
                cp16(smu + SM_PRE + (uint32_t)(row * 128 + q * 16),
                     &pre[(size_t)(brow + row) * row_stride + bcol + q * 4]);
            }
            cp_commit();
            asm volatile("cp.async.wait_group 0;");
            __syncthreads();
        }

        // ---- merge k-group partials ----
        float c0 = 0.f, c1 = 0.f, c2 = 0.f, c3 = 0.f;
#pragma unroll
        for (int i = 0; i < 6; i++) {
            c0 += acc[i][0]; c1 += acc[i][1];
            c2 += acc[i][2]; c3 += acc[i][3];
        }
        if (t > 0) {
            if (kg == 1) {
                asm volatile("st.shared.v4.f32 [%0], {%1,%2,%3,%4};"
                             :: "r"(scr), "f"(c0), "f"(c1), "f"(c2), "f"(c3)
                             : "memory");
            }
            __syncthreads();
        }

        // ---- epilogue (kg==0 warps): h = tanh(pre + acc) ----
        const int gid = lane >> 2;
        const int tig = lane & 3;
        const int m0 = brow + gid;
        const int m1 = m0 + 8;
        const int nc = bcol + nt * 8 + tig * 2;
        float h00, h01, h10, h11;

        if (kg == 0) {
            if (t > 0) {
                float s0, s1, s2, s3;
                asm volatile("ld.shared.v4.f32 {%0,%1,%2,%3}, [%4];"
                             : "=f"(s0), "=f"(s1), "=f"(s2), "=f"(s3) : "r"(scr));
                c0 += s0; c1 += s1; c2 += s2; c3 += s3;
            }
            const uint32_t pofs = (uint32_t)((nt * 8 + tig * 2) * 4);
            float2 p0 = *(const float2*)(smb + SM_PRE + gid * 128 + pofs);
            float2 p1 = *(const float2*)(smb + SM_PRE + (gid + 8) * 128 + pofs);
            h00 = tanhf(p0.x + c0);
            h01 = tanhf(p0.y + c1);
            h10 = tanhf(p1.x + c2);
            h11 = tanhf(p1.y + c3);

            // state for next step (what peer blocks need) — store FIRST
            __nv_bfloat16 e00 = __float2bfloat16(h00);
            __nv_bfloat16 e01 = __float2bfloat16(h01);
            __nv_bfloat16 e10 = __float2bfloat16(h10);
            __nv_bfloat16 e11 = __float2bfloat16(h11);
            *(uint32_t*)&g_hhi[(size_t)m0 * HH + nc] = pack_bf16(h00, h01);
            *(uint32_t*)&g_hhi[(size_t)m1 * HH + nc] = pack_bf16(h10, h11);
            *(uint32_t*)&g_hlo[(size_t)m0 * HH + nc] =
                pack_bf16(h00 - __bfloat162float(e00), h01 - __bfloat162float(e01));
            *(uint32_t*)&g_hlo[(size_t)m1 * HH + nc] =
                pack_bf16(h10 - __bfloat162float(e10), h11 - __bfloat162float(e11));
        }

        // ---- barrier: arrive early, then drain fp32 output off-path ----
        __syncthreads();
        __threadfence();
        unsigned int mygen = 0;
        if (tid == 0) {
            mygen = g_bar_gen[rg];
            unsigned int tkt = atomicAdd(&g_bar_count[rg], 1u);
            if (tkt == NCOLBLK - 1) {
                g_bar_count[rg] = 0;
                __threadfence();
                g_bar_gen[rg] = mygen + 1;
            }
        }
        if (kg == 0) {
            const size_t o0 = (size_t)m0 * row_stride + (size_t)t * HH + nc;
            const size_t o1 = (size_t)m1 * row_stride + (size_t)t * HH + nc;
            *(float2*)&hbase[o0] = make_float2(h00, h01);
            *(float2*)&hbase[o1] = make_float2(h10, h11);
        }
        if (tid == 0) {
            while (g_bar_gen[rg] == mygen) { }
        }
        __syncthreads();
    }
}

// ---------------------------------------------------------------------------
__global__ void finalize_kernel(float* __restrict__ out)
{
    int i = blockIdx.x * blockDim.x + threadIdx.x;   // over B*H
    if (i >= BB * HH) return;
    int b = i / HH;
    int h = i - b * HH;
    float* hfin = out + (size_t)BB * TT * HH;
    size_t src = (size_t)b * TT * HH + (size_t)(TT - 1) * HH + h;
    hfin[i] = g_buf0[src];
    hfin[(size_t)BB * HH + i] = out[src];
}

// ---------------------------------------------------------------------------

extern "C" void kernel_launch(void* const* d_in, const int* in_sizes, int n_in,
                              void* d_out, int out_size)
{
    const float* x      = (const float*)d_in[0];
    const float* W_ih0  = (const float*)d_in[1];
    const float* W_hh0  = (const float*)d_in[2];
    const float* b_ih0  = (const float*)d_in[3];
    const float* b_hh0  = (const float*)d_in[4];
    const float* W_ih1  = (const float*)d_in[5];
    const float* W_hh1  = (const float*)d_in[6];
    const float* b_ih1  = (const float*)d_in[7];
    const float* b_hh1  = (const float*)d_in[8];
    float* out = (float*)d_out;

    void* p;
    cudaGetSymbolAddress(&p, g_buf0); float* buf0 = (float*)p;
    cudaGetSymbolAddress(&p, g_buf1); float* buf1 = (float*)p;
    cudaGetSymbolAddress(&p, g_ahi);  __nv_bfloat16* ahi = (__nv_bfloat16*)p;
    cudaGetSymbolAddress(&p, g_alo);  __nv_bfloat16* alo = (__nv_bfloat16*)p;
    cudaGetSymbolAddress(&p, g_whi);  __nv_bfloat16* whi = (__nv_bfloat16*)p;
    cudaGetSymbolAddress(&p, g_wlo);  __nv_bfloat16* wlo = (__nv_bfloat16*)p;

    cudaFuncSetAttribute(rnn_layer_tc,
                         cudaFuncAttributeMaxDynamicSharedMemorySize, SM_TOTAL);
    cudaFuncSetAttribute(hmma_pre_gemm,
                         cudaFuncAttributeMaxDynamicSharedMemorySize, P_SMEM);

    // 1) split X and W_ih0 to bf16 hi/lo
    conv_split_kernel<<<1024, 256>>>(x, ahi, alo, BB * TT * DIN);
    conv_split_kernel<<<256, 256>>>(W_ih0, whi, wlo, HH * DIN);

    // 2) pre0 = X @ W_ih0^T + b_ih0 + b_hh0
    {
        dim3 grid(HH / 64, (BB * TT) / 128);
        hmma_pre_gemm<<<grid, 256, P_SMEM>>>(ahi, alo, whi, wlo,
                                             b_ih0, b_hh0, buf0, DIN);
    }

    // 3) layer-0 recurrence (in place over buf0)
    rnn_layer_tc<<<RNBLK, NTHR, SM_TOTAL>>>(buf0, buf0, W_hh0);

    // 4) split H0 and W_ih1, then pre1 = H0 @ W_ih1^T + b_ih1 + b_hh1
    conv_split_kernel<<<1024, 256>>>(buf0, ahi, alo, BB * TT * HH);
    conv_split_kernel<<<512, 256>>>(W_ih1, whi, wlo, HH * HH);
    {
        dim3 grid(HH / 64, (BB * TT) / 128);
        hmma_pre_gemm<<<grid, 256, P_SMEM>>>(ahi, alo, whi, wlo,
                                             b_ih1, b_hh1, buf1, HH);
    }

    // 5) layer-1 recurrence (writes h1 into outputs region)
    rnn_layer_tc<<<RNBLK, NTHR, SM_TOTAL>>>(buf1, out, W_hh1);

    // 6) h_final
    finalize_kernel<<<(BB * HH + 255) / 256, 256>>>(out);
}